// round 14
// baseline (speedup 1.0000x reference)
#include <cuda_runtime.h>
#include <cuda_fp16.h>
#include <math.h>

// IDXST_IDCT 4096x4096, half-length Hermitian FFT per row; fp16 intermediates.
//   A[m] = FFT_N(x * expk);  idct = Re A, idxst = Im A.
//   d[k] = 0.5*expk[k]*(X[k]+j X[N-k]) (MODE0) / -(X[N-k]+j X[k]) (MODE1)
//   E=d[k]+d[k+H], O=(d[k]-d[k+H])*W_N^k, z=E+jO, Z=FFT_H(z)
//   u[2n]=Re Z[n], u[2n+1]=Im Z[n];  expk[k+H]=expk[k]*e^{-j pi/4}; W_N^k=expk[k]^4.
// fft16 = radix-2 DIF + two in-place fft8s (low register pressure) with the
// even/odd output mapping folded into twiddle_store_split. Final stage computes
// butterflies q=t / q'=255-t so the epilogue is entirely in registers (R13).
// Pipeline: rowK(x fp32, expkN) -> half -> T(h->h) -> rowK(half, expkM) -> half -> T(h->f32)

#define LROW 4096
#define HN 2048
#define FFT_T 128
#define PADSZ (HN + HN / 16)  // 2176 float2 slots (17408 B)

__device__ float2 g_tA[128];  // W_2048^t
__device__ float2 g_tB[8];    // W_128^p
__device__ __half g_bufh0[(size_t)LROW * LROW];
__device__ __half g_bufh1[(size_t)LROW * LROW];

struct __align__(8) H4 { __half2 lo, hi; };

__device__ __forceinline__ float2 cmul(float2 a, float2 b) {
    return make_float2(a.x * b.x - a.y * b.y, a.x * b.y + a.y * b.x);
}
__device__ __forceinline__ float2 cadd(float2 a, float2 b) {
    return make_float2(a.x + b.x, a.y + b.y);
}
__device__ __forceinline__ float2 csub(float2 a, float2 b) {
    return make_float2(a.x - b.x, a.y - b.y);
}

// e^{-2pi j k/16}, k=0..9
__constant__ float2 c_tw16[10] = {
    {1.f, 0.f},
    {0.92387953251128674f, -0.38268343236508978f},
    {0.70710678118654757f, -0.70710678118654757f},
    {0.38268343236508978f, -0.92387953251128674f},
    {0.f, -1.f},
    {-0.38268343236508978f, -0.92387953251128674f},
    {-0.70710678118654757f, -0.70710678118654757f},
    {-0.92387953251128674f, -0.38268343236508978f},
    {-1.f, 0.f},
    {-0.92387953251128674f, 0.38268343236508978f}};

__global__ void init_twiddles_kernel() {
    int t = threadIdx.x;  // 136 threads
    double s, c;
    if (t < 128) {
        sincospi(-(double)t / 1024.0, &s, &c);
        g_tA[t] = make_float2((float)c, (float)s);
    } else {
        int p = t - 128;
        sincospi(-(double)p / 64.0, &s, &c);
        g_tB[p] = make_float2((float)c, (float)s);
    }
}

// In-place natural-order 8-point DFT, generic stride (template keeps it compile-time).
template <int S>
__device__ __forceinline__ void fft8_ip(float2* x) {
    float2 x0 = x[0], x1 = x[S], x2 = x[2 * S], x3 = x[3 * S];
    float2 x4 = x[4 * S], x5 = x[5 * S], x6 = x[6 * S], x7 = x[7 * S];
    float2 apc = cadd(x0, x4), amc = csub(x0, x4);
    float2 bpd = cadd(x2, x6), bmd = csub(x2, x6);
    float2 jb = make_float2(-bmd.y, bmd.x);
    float2 e0 = cadd(apc, bpd), e1 = csub(amc, jb);
    float2 e2 = csub(apc, bpd), e3 = cadd(amc, jb);
    apc = cadd(x1, x5); amc = csub(x1, x5);
    bpd = cadd(x3, x7); bmd = csub(x3, x7);
    jb = make_float2(-bmd.y, bmd.x);
    float2 o0 = cadd(apc, bpd), o1 = csub(amc, jb);
    float2 o2 = csub(apc, bpd), o3 = cadd(amc, jb);
    const float s = 0.70710678118654757f;
    float2 w1o = make_float2(s * (o1.x + o1.y), s * (o1.y - o1.x));
    float2 w2o = make_float2(o2.y, -o2.x);
    float2 w3o = make_float2(s * (o3.y - o3.x), -s * (o3.x + o3.y));
    x[0] = cadd(e0, o0);      x[4 * S] = csub(e0, o0);
    x[S] = cadd(e1, w1o);     x[5 * S] = csub(e1, w1o);
    x[2 * S] = cadd(e2, w2o); x[6 * S] = csub(e2, w2o);
    x[3 * S] = cadd(e3, w3o); x[7 * S] = csub(e3, w3o);
}

// 16-point DFT, low-register split form: radix-2 DIF + two in-place fft8s.
// Output mapping: r[i] = Y[2i], r[8+i] = Y[2i+1] (i<8).
__device__ __forceinline__ void fft16s(float2 r[16]) {
#pragma unroll
    for (int i = 0; i < 8; i++) {
        float2 d = csub(r[i], r[i + 8]);
        r[i] = cadd(r[i], r[i + 8]);
        r[i + 8] = (i == 0) ? d : cmul(d, c_tw16[i]);  // *W16^i
    }
    fft8_ip<1>(&r[0]);  // -> Y[2m]
    fft8_ip<1>(&r[8]);  // -> Y[2m+1]
}

// Store Y[i]*w^i using the split layout: r[i]=Y[2i], r[8+i]=Y[2i+1].
//   dst[2i*stride]   = r[i]   * (w^2)^i
//   dst[(2i+1)*stride] = (w*r[8+i]) * (w^2)^i
__device__ __forceinline__ void twiddle_store_split(float2* dst, int stride,
                                                    const float2 r[16], float2 w) {
    float2 u1 = cmul(w, w);        // w^2
    float2 u2 = cmul(u1, u1);      // w^4
    float2 u3 = cmul(u2, u1);      // w^6
    float2 u4 = cmul(u2, u2);      // w^8
    float2 u5 = cmul(u4, u1);      // w^10
    float2 u6 = cmul(u4, u2);      // w^12
    float2 u7 = cmul(u4, u3);      // w^14
    dst[0] = r[0];
    dst[2 * stride] = cmul(r[1], u1);
    dst[4 * stride] = cmul(r[2], u2);
    dst[6 * stride] = cmul(r[3], u3);
    dst[8 * stride] = cmul(r[4], u4);
    dst[10 * stride] = cmul(r[5], u5);
    dst[12 * stride] = cmul(r[6], u6);
    dst[14 * stride] = cmul(r[7], u7);
    float2 v0 = cmul(r[8], w);
    float2 v1 = cmul(r[9], w);
    float2 v2 = cmul(r[10], w);
    float2 v3 = cmul(r[11], w);
    float2 v4 = cmul(r[12], w);
    float2 v5 = cmul(r[13], w);
    float2 v6 = cmul(r[14], w);
    float2 v7 = cmul(r[15], w);
    dst[1 * stride] = v0;
    dst[3 * stride] = cmul(v1, u1);
    dst[5 * stride] = cmul(v2, u2);
    dst[7 * stride] = cmul(v3, u3);
    dst[9 * stride] = cmul(v4, u4);
    dst[11 * stride] = cmul(v5, u5);
    dst[13 * stride] = cmul(v6, u6);
    dst[15 * stride] = cmul(v7, u7);
}

// MODE 0: IDCT (u = Re A).  MODE 1: IDXST (u = Im A, se negated).
// HALF_IN: input matrix is fp16 (intermediate) vs fp32 (original x).
template <int MODE, bool HALF_IN>
__global__ __launch_bounds__(FFT_T, 10) void fft_row_kernel(
    const void* __restrict__ in_, const float2* __restrict__ expk,
    __half* __restrict__ out) {
    extern __shared__ float2 sm2[];
    float* sraw = reinterpret_cast<float*>(sm2);
    const int t = threadIdx.x;
    const size_t row = blockIdx.x;

    // Stage full row into smem as fp32, coalesced vector loads. (R9-verified)
    if (!HALF_IN) {
        const float4* __restrict__ x4 =
            reinterpret_cast<const float4*>((const float*)in_ + row * LROW);
        float4* s4 = reinterpret_cast<float4*>(sraw);
#pragma unroll
        for (int i = 0; i < 8; i++) s4[t + 128 * i] = x4[t + 128 * i];
    } else {
        const uint4* __restrict__ x4 =
            reinterpret_cast<const uint4*>((const __half*)in_ + row * LROW);
        float4* s4 = reinterpret_cast<float4*>(sraw);
#pragma unroll
        for (int i = 0; i < 4; i++) {
            uint4 u = x4[t + 128 * i];
            __half2 h[4];
            *reinterpret_cast<uint4*>(h) = u;
            float2 f0 = __half22float2(h[0]);
            float2 f1 = __half22float2(h[1]);
            float2 f2 = __half22float2(h[2]);
            float2 f3 = __half22float2(h[3]);
            s4[2 * (t + 128 * i)] = make_float4(f0.x, f0.y, f1.x, f1.y);
            s4[2 * (t + 128 * i) + 1] = make_float4(f2.x, f2.y, f3.x, f3.y);
        }
    }
    __syncthreads();

    const float2 C8 = make_float2(0.70710678118654757f, -0.70710678118654757f);
    float2 r[16];
#pragma unroll
    for (int i = 0; i < 16; i++) {
        const int k = t + 128 * i;  // k < 2048
        float a = sraw[k];
        float b = sraw[(LROW - k) & (LROW - 1)];
        float a2 = sraw[k + HN];
        float b2 = sraw[HN - k];
        float2 e = expk[k];
        float2 e2 = cmul(e, C8);      // expk[k+2048]
        float2 esq = cmul(e, e);
        float2 w4k = cmul(esq, esq);  // W_4096^k
        float2 v1, v2;
        if (MODE == 0) {
            v1 = make_float2(a, b);
            v2 = make_float2(a2, b2);
        } else {
            v1 = make_float2(-b, -a);
            v2 = make_float2(-b2, -a2);
        }
        float2 dk = cmul(e, v1);
        float2 dk2 = cmul(e2, v2);
        if (k == 0) dk = make_float2(MODE == 0 ? 2.f * a : 0.f, 0.f);
        float2 E = cadd(dk, dk2);
        float2 Od = csub(dk, dk2);
        float2 O = cmul(Od, w4k);
        r[i] = make_float2(E.x - O.y, E.y + O.x);  // z = E + j*O
    }
    __syncthreads();  // all sraw reads done before workspace writes

    // ---- FFT_2048, Stockham radix 16*16*8, 128 threads x 16 regs ----
    fft16s(r);
    twiddle_store_split(&sm2[17 * t], 1, r, g_tA[t]);
    __syncthreads();
    const int rb = t + (t >> 4);
#pragma unroll
    for (int i = 0; i < 16; i++) r[i] = sm2[rb + 136 * i];  // X[t+128i]
    __syncthreads();

    fft16s(r);
    twiddle_store_split(&sm2[(t & 15) + 272 * (t >> 4)], 17, r, g_tB[t >> 4]);
    __syncthreads();

    // Second exchange, re-assigned for the register epilogue:
    //   even regs r[2u]   = X[t + 256u]        (butterfly q  = t)
    //   odd  regs r[2u+1] = X[(255-t) + 256u]  (butterfly q' = 255-t)
    const int tr = 255 - t;
    const int rb2 = tr + (tr >> 4);
#pragma unroll
    for (int u = 0; u < 8; u++) {
        r[2 * u] = sm2[rb + 272 * u];
        r[2 * u + 1] = sm2[rb2 + 272 * u];
    }

    fft8_ip<2>(&r[0]);  // -> r[2i]   = Z[t + 256i]
    fft8_ip<2>(&r[1]);  // -> r[2i+1] = Z[(255-t) + 256i]

    // Register epilogue (R13): quad c needs Z[c] and Z[2047-c].
    const float se = (MODE == 0) ? 0.5f : -0.5f;
    H4* __restrict__ o4 = reinterpret_cast<H4*>(out + row * LROW);
#pragma unroll
    for (int u = 0; u < 4; u++) {
        int c = t + 256 * u;  // < 1024
        float2 zc = r[2 * u];
        float2 zr = r[2 * (7 - u) + 1];
        H4 h;
        h.lo = __floats2half2_rn(se * zc.x, 0.5f * zr.y);
        h.hi = __floats2half2_rn(se * zc.y, 0.5f * zr.x);
        o4[c] = h;
    }
#pragma unroll
    for (int v = 0; v < 4; v++) {
        int c = tr + 256 * v;  // < 1024
        float2 zc = r[2 * v + 1];
        float2 zr = r[2 * (7 - v)];
        H4 h;
        h.lo = __floats2half2_rn(se * zc.x, 0.5f * zr.y);
        h.hi = __floats2half2_rn(se * zc.y, 0.5f * zr.x);
        o4[c] = h;
    }
}

// 64x64 half transpose, 128 threads, 4 batched uint4 loads/thread for MLP.
// OUT_FLOAT: convert to fp32 on store (final pass).
template <bool OUT_FLOAT>
__global__ __launch_bounds__(128) void transpose_h_kernel(
    const __half* __restrict__ in, void* __restrict__ out_) {
    __shared__ __half tile[64][65];
    const int x0 = blockIdx.x * 64, y0 = blockIdx.y * 64;
    const int tx = threadIdx.x & 7;   // 0..7
    const int ty = threadIdx.x >> 3;  // 0..15

    uint4 u[4];
#pragma unroll
    for (int j = 0; j < 4; j++) {
        int r = ty + 16 * j;
        u[j] = *reinterpret_cast<const uint4*>(&in[(size_t)(y0 + r) * LROW + x0 + 8 * tx]);
    }
#pragma unroll
    for (int j = 0; j < 4; j++) {
        int r = ty + 16 * j;
        __half tmp[8];
        *reinterpret_cast<uint4*>(tmp) = u[j];
#pragma unroll
        for (int q = 0; q < 8; q++) tile[8 * tx + q][r] = tmp[q];
    }
    __syncthreads();

#pragma unroll
    for (int j = 0; j < 4; j++) {
        int c = ty + 16 * j;  // out row = x0 + c, cols y0 + 8tx .. +7
        if (OUT_FLOAT) {
            float* out = (float*)out_;
            float4 v0, v1;
            v0.x = __half2float(tile[c][8 * tx + 0]);
            v0.y = __half2float(tile[c][8 * tx + 1]);
            v0.z = __half2float(tile[c][8 * tx + 2]);
            v0.w = __half2float(tile[c][8 * tx + 3]);
            v1.x = __half2float(tile[c][8 * tx + 4]);
            v1.y = __half2float(tile[c][8 * tx + 5]);
            v1.z = __half2float(tile[c][8 * tx + 6]);
            v1.w = __half2float(tile[c][8 * tx + 7]);
            float4* o = reinterpret_cast<float4*>(&out[(size_t)(x0 + c) * LROW + y0 + 8 * tx]);
            o[0] = v0;
            o[1] = v1;
        } else {
            __half* out = (__half*)out_;
            __half tmp[8];
#pragma unroll
            for (int q = 0; q < 8; q++) tmp[q] = tile[c][8 * tx + q];
            *reinterpret_cast<uint4*>(&out[(size_t)(x0 + c) * LROW + y0 + 8 * tx]) =
                *reinterpret_cast<uint4*>(tmp);
        }
    }
}

extern "C" void kernel_launch(void* const* d_in, const int* in_sizes, int n_in,
                              void* d_out, int out_size) {
    const float* x = (const float*)d_in[0];
    const float2* expkM = (const float2*)d_in[1];
    const float2* expkN = (const float2*)d_in[2];
    float* out = (float*)d_out;

    __half *bh0, *bh1;
    cudaGetSymbolAddress((void**)&bh0, g_bufh0);
    cudaGetSymbolAddress((void**)&bh1, g_bufh1);

    const size_t smem = (size_t)PADSZ * sizeof(float2);  // 17408 B
    dim3 tg(64, 64);

    init_twiddles_kernel<<<1, 136>>>();
    fft_row_kernel<0, false><<<LROW, FFT_T, smem>>>(x, expkN, bh0);   // t (fp16)
    transpose_h_kernel<false><<<tg, 128>>>(bh0, bh1);                 // t^T (fp16)
    fft_row_kernel<1, true><<<LROW, FFT_T, smem>>>(bh1, expkM, bh0);  // y^T (fp16)
    transpose_h_kernel<true><<<tg, 128>>>(bh0, out);                  // y (fp32)
}

// round 15
// speedup vs baseline: 1.0524x; 1.0524x over previous
#include <cuda_runtime.h>
#include <cuda_fp16.h>
#include <math.h>

// IDXST_IDCT 4096x4096, half-length Hermitian FFT per row; fp16 intermediates.
//   A[m] = FFT_N(x * expk);  idct = Re A, idxst = Im A.
//   d[k] = 0.5*expk[k]*(X[k]+j X[N-k]) (MODE0) / -(X[N-k]+j X[k]) (MODE1)
//   E=d[k]+d[k+H], O=(d[k]-d[k+H])*W_N^k, z=E+jO, Z=FFT_H(z)
//   u[2n]=Re Z[n], u[2n+1]=Im Z[n];  expk[k+H]=expk[k]*e^{-j pi/4}; W_N^k=expk[k]^4.
// Stage twiddles W_2048^t / W_128^p computed inline with __sincosf (no tables,
// no init kernel). fft16 = radix-2 DIF + two in-place fft8s (48 regs). Final
// stage computes butterflies q=t / q'=255-t -> epilogue entirely in registers.
// Pipeline: rowK(x fp32, expkN) -> half -> T(h->h) -> rowK(half, expkM) -> half -> T(h->f32)

#define LROW 4096
#define HN 2048
#define FFT_T 128
#define PADSZ (HN + HN / 16)  // 2176 float2 slots (17408 B)

__device__ __half g_bufh0[(size_t)LROW * LROW];
__device__ __half g_bufh1[(size_t)LROW * LROW];

struct __align__(8) H4 { __half2 lo, hi; };

__device__ __forceinline__ float2 cmul(float2 a, float2 b) {
    return make_float2(a.x * b.x - a.y * b.y, a.x * b.y + a.y * b.x);
}
__device__ __forceinline__ float2 cadd(float2 a, float2 b) {
    return make_float2(a.x + b.x, a.y + b.y);
}
__device__ __forceinline__ float2 csub(float2 a, float2 b) {
    return make_float2(a.x - b.x, a.y - b.y);
}

// e^{-2pi j k/16}, k=0..9
__constant__ float2 c_tw16[10] = {
    {1.f, 0.f},
    {0.92387953251128674f, -0.38268343236508978f},
    {0.70710678118654757f, -0.70710678118654757f},
    {0.38268343236508978f, -0.92387953251128674f},
    {0.f, -1.f},
    {-0.38268343236508978f, -0.92387953251128674f},
    {-0.70710678118654757f, -0.70710678118654757f},
    {-0.92387953251128674f, -0.38268343236508978f},
    {-1.f, 0.f},
    {-0.92387953251128674f, 0.38268343236508978f}};

// In-place natural-order 8-point DFT, generic stride.
template <int S>
__device__ __forceinline__ void fft8_ip(float2* x) {
    float2 x0 = x[0], x1 = x[S], x2 = x[2 * S], x3 = x[3 * S];
    float2 x4 = x[4 * S], x5 = x[5 * S], x6 = x[6 * S], x7 = x[7 * S];
    float2 apc = cadd(x0, x4), amc = csub(x0, x4);
    float2 bpd = cadd(x2, x6), bmd = csub(x2, x6);
    float2 jb = make_float2(-bmd.y, bmd.x);
    float2 e0 = cadd(apc, bpd), e1 = csub(amc, jb);
    float2 e2 = csub(apc, bpd), e3 = cadd(amc, jb);
    apc = cadd(x1, x5); amc = csub(x1, x5);
    bpd = cadd(x3, x7); bmd = csub(x3, x7);
    jb = make_float2(-bmd.y, bmd.x);
    float2 o0 = cadd(apc, bpd), o1 = csub(amc, jb);
    float2 o2 = csub(apc, bpd), o3 = cadd(amc, jb);
    const float s = 0.70710678118654757f;
    float2 w1o = make_float2(s * (o1.x + o1.y), s * (o1.y - o1.x));
    float2 w2o = make_float2(o2.y, -o2.x);
    float2 w3o = make_float2(s * (o3.y - o3.x), -s * (o3.x + o3.y));
    x[0] = cadd(e0, o0);      x[4 * S] = csub(e0, o0);
    x[S] = cadd(e1, w1o);     x[5 * S] = csub(e1, w1o);
    x[2 * S] = cadd(e2, w2o); x[6 * S] = csub(e2, w2o);
    x[3 * S] = cadd(e3, w3o); x[7 * S] = csub(e3, w3o);
}

// 16-point DFT, low-register split form: radix-2 DIF + two in-place fft8s.
// Output mapping: r[i] = Y[2i], r[8+i] = Y[2i+1] (i<8).
__device__ __forceinline__ void fft16s(float2 r[16]) {
#pragma unroll
    for (int i = 0; i < 8; i++) {
        float2 d = csub(r[i], r[i + 8]);
        r[i] = cadd(r[i], r[i + 8]);
        r[i + 8] = (i == 0) ? d : cmul(d, c_tw16[i]);  // *W16^i
    }
    fft8_ip<1>(&r[0]);  // -> Y[2m]
    fft8_ip<1>(&r[8]);  // -> Y[2m+1]
}

// Store Y[i]*w^i using the split layout: r[i]=Y[2i], r[8+i]=Y[2i+1].
__device__ __forceinline__ void twiddle_store_split(float2* dst, int stride,
                                                    const float2 r[16], float2 w) {
    float2 u1 = cmul(w, w);        // w^2
    float2 u2 = cmul(u1, u1);      // w^4
    float2 u3 = cmul(u2, u1);      // w^6
    float2 u4 = cmul(u2, u2);      // w^8
    float2 u5 = cmul(u4, u1);      // w^10
    float2 u6 = cmul(u4, u2);      // w^12
    float2 u7 = cmul(u4, u3);      // w^14
    dst[0] = r[0];
    dst[2 * stride] = cmul(r[1], u1);
    dst[4 * stride] = cmul(r[2], u2);
    dst[6 * stride] = cmul(r[3], u3);
    dst[8 * stride] = cmul(r[4], u4);
    dst[10 * stride] = cmul(r[5], u5);
    dst[12 * stride] = cmul(r[6], u6);
    dst[14 * stride] = cmul(r[7], u7);
    float2 v0 = cmul(r[8], w);
    float2 v1 = cmul(r[9], w);
    float2 v2 = cmul(r[10], w);
    float2 v3 = cmul(r[11], w);
    float2 v4 = cmul(r[12], w);
    float2 v5 = cmul(r[13], w);
    float2 v6 = cmul(r[14], w);
    float2 v7 = cmul(r[15], w);
    dst[1 * stride] = v0;
    dst[3 * stride] = cmul(v1, u1);
    dst[5 * stride] = cmul(v2, u2);
    dst[7 * stride] = cmul(v3, u3);
    dst[9 * stride] = cmul(v4, u4);
    dst[11 * stride] = cmul(v5, u5);
    dst[13 * stride] = cmul(v6, u6);
    dst[15 * stride] = cmul(v7, u7);
}

// MODE 0: IDCT (u = Re A).  MODE 1: IDXST (u = Im A, se negated).
// HALF_IN: input matrix is fp16 (intermediate) vs fp32 (original x).
template <int MODE, bool HALF_IN>
__global__ __launch_bounds__(FFT_T, 10) void fft_row_kernel(
    const void* __restrict__ in_, const float2* __restrict__ expk,
    __half* __restrict__ out) {
    extern __shared__ float2 sm2[];
    float* sraw = reinterpret_cast<float*>(sm2);
    const int t = threadIdx.x;
    const size_t row = blockIdx.x;

    // Stage-twiddles computed inline (args in [-0.4, 0]; __sincosf exact enough:
    // worst error after the w^14 power tree ~1e-6, far below fp16 noise 3e-4).
    float2 wA, wB;
    {
        float s, c;
        __sincosf(-3.14159265358979323846f * (float)t / 1024.0f, &s, &c);
        wA = make_float2(c, s);  // W_2048^t
        __sincosf(-3.14159265358979323846f * (float)(t >> 4) / 64.0f, &s, &c);
        wB = make_float2(c, s);  // W_128^(t>>4)
    }

    // Stage full row into smem as fp32, coalesced vector loads. (R9-verified)
    if (!HALF_IN) {
        const float4* __restrict__ x4 =
            reinterpret_cast<const float4*>((const float*)in_ + row * LROW);
        float4* s4 = reinterpret_cast<float4*>(sraw);
#pragma unroll
        for (int i = 0; i < 8; i++) s4[t + 128 * i] = x4[t + 128 * i];
    } else {
        const uint4* __restrict__ x4 =
            reinterpret_cast<const uint4*>((const __half*)in_ + row * LROW);
        float4* s4 = reinterpret_cast<float4*>(sraw);
#pragma unroll
        for (int i = 0; i < 4; i++) {
            uint4 u = x4[t + 128 * i];
            __half2 h[4];
            *reinterpret_cast<uint4*>(h) = u;
            float2 f0 = __half22float2(h[0]);
            float2 f1 = __half22float2(h[1]);
            float2 f2 = __half22float2(h[2]);
            float2 f3 = __half22float2(h[3]);
            s4[2 * (t + 128 * i)] = make_float4(f0.x, f0.y, f1.x, f1.y);
            s4[2 * (t + 128 * i) + 1] = make_float4(f2.x, f2.y, f3.x, f3.y);
        }
    }
    __syncthreads();

    const float2 C8 = make_float2(0.70710678118654757f, -0.70710678118654757f);
    float2 r[16];
#pragma unroll
    for (int i = 0; i < 16; i++) {
        const int k = t + 128 * i;  // k < 2048
        float a = sraw[k];
        float b = sraw[(LROW - k) & (LROW - 1)];
        float a2 = sraw[k + HN];
        float b2 = sraw[HN - k];
        float2 e = expk[k];
        float2 e2 = cmul(e, C8);      // expk[k+2048]
        float2 esq = cmul(e, e);
        float2 w4k = cmul(esq, esq);  // W_4096^k
        float2 v1, v2;
        if (MODE == 0) {
            v1 = make_float2(a, b);
            v2 = make_float2(a2, b2);
        } else {
            v1 = make_float2(-b, -a);
            v2 = make_float2(-b2, -a2);
        }
        float2 dk = cmul(e, v1);
        float2 dk2 = cmul(e2, v2);
        if (k == 0) dk = make_float2(MODE == 0 ? 2.f * a : 0.f, 0.f);
        float2 E = cadd(dk, dk2);
        float2 Od = csub(dk, dk2);
        float2 O = cmul(Od, w4k);
        r[i] = make_float2(E.x - O.y, E.y + O.x);  // z = E + j*O
    }
    __syncthreads();  // all sraw reads done before workspace writes

    // ---- FFT_2048, Stockham radix 16*16*8, 128 threads x 16 regs ----
    fft16s(r);
    twiddle_store_split(&sm2[17 * t], 1, r, wA);
    __syncthreads();
    const int rb = t + (t >> 4);
#pragma unroll
    for (int i = 0; i < 16; i++) r[i] = sm2[rb + 136 * i];  // X[t+128i]
    __syncthreads();

    fft16s(r);
    twiddle_store_split(&sm2[(t & 15) + 272 * (t >> 4)], 17, r, wB);
    __syncthreads();

    // Second exchange, re-assigned for the register epilogue:
    //   even regs r[2u]   = X[t + 256u]        (butterfly q  = t)
    //   odd  regs r[2u+1] = X[(255-t) + 256u]  (butterfly q' = 255-t)
    const int tr = 255 - t;
    const int rb2 = tr + (tr >> 4);
#pragma unroll
    for (int u = 0; u < 8; u++) {
        r[2 * u] = sm2[rb + 272 * u];
        r[2 * u + 1] = sm2[rb2 + 272 * u];
    }

    fft8_ip<2>(&r[0]);  // -> r[2i]   = Z[t + 256i]
    fft8_ip<2>(&r[1]);  // -> r[2i+1] = Z[(255-t) + 256i]

    // Register epilogue (R13): quad c needs Z[c] and Z[2047-c].
    const float se = (MODE == 0) ? 0.5f : -0.5f;
    H4* __restrict__ o4 = reinterpret_cast<H4*>(out + row * LROW);
#pragma unroll
    for (int u = 0; u < 4; u++) {
        int c = t + 256 * u;  // < 1024
        float2 zc = r[2 * u];
        float2 zr = r[2 * (7 - u) + 1];
        H4 h;
        h.lo = __floats2half2_rn(se * zc.x, 0.5f * zr.y);
        h.hi = __floats2half2_rn(se * zc.y, 0.5f * zr.x);
        o4[c] = h;
    }
#pragma unroll
    for (int v = 0; v < 4; v++) {
        int c = tr + 256 * v;  // < 1024
        float2 zc = r[2 * v + 1];
        float2 zr = r[2 * (7 - v)];
        H4 h;
        h.lo = __floats2half2_rn(se * zc.x, 0.5f * zr.y);
        h.hi = __floats2half2_rn(se * zc.y, 0.5f * zr.x);
        o4[c] = h;
    }
}

// 64x64 half transpose, 128 threads, 4 batched uint4 loads/thread for MLP.
// OUT_FLOAT: convert to fp32 on store (final pass).
template <bool OUT_FLOAT>
__global__ __launch_bounds__(128) void transpose_h_kernel(
    const __half* __restrict__ in, void* __restrict__ out_) {
    __shared__ __half tile[64][65];
    const int x0 = blockIdx.x * 64, y0 = blockIdx.y * 64;
    const int tx = threadIdx.x & 7;   // 0..7
    const int ty = threadIdx.x >> 3;  // 0..15

    uint4 u[4];
#pragma unroll
    for (int j = 0; j < 4; j++) {
        int r = ty + 16 * j;
        u[j] = *reinterpret_cast<const uint4*>(&in[(size_t)(y0 + r) * LROW + x0 + 8 * tx]);
    }
#pragma unroll
    for (int j = 0; j < 4; j++) {
        int r = ty + 16 * j;
        __half tmp[8];
        *reinterpret_cast<uint4*>(tmp) = u[j];
#pragma unroll
        for (int q = 0; q < 8; q++) tile[8 * tx + q][r] = tmp[q];
    }
    __syncthreads();

#pragma unroll
    for (int j = 0; j < 4; j++) {
        int c = ty + 16 * j;  // out row = x0 + c, cols y0 + 8tx .. +7
        if (OUT_FLOAT) {
            float* out = (float*)out_;
            float4 v0, v1;
            v0.x = __half2float(tile[c][8 * tx + 0]);
            v0.y = __half2float(tile[c][8 * tx + 1]);
            v0.z = __half2float(tile[c][8 * tx + 2]);
            v0.w = __half2float(tile[c][8 * tx + 3]);
            v1.x = __half2float(tile[c][8 * tx + 4]);
            v1.y = __half2float(tile[c][8 * tx + 5]);
            v1.z = __half2float(tile[c][8 * tx + 6]);
            v1.w = __half2float(tile[c][8 * tx + 7]);
            float4* o = reinterpret_cast<float4*>(&out[(size_t)(x0 + c) * LROW + y0 + 8 * tx]);
            o[0] = v0;
            o[1] = v1;
        } else {
            __half* out = (__half*)out_;
            __half tmp[8];
#pragma unroll
            for (int q = 0; q < 8; q++) tmp[q] = tile[c][8 * tx + q];
            *reinterpret_cast<uint4*>(&out[(size_t)(x0 + c) * LROW + y0 + 8 * tx]) =
                *reinterpret_cast<uint4*>(tmp);
        }
    }
}

extern "C" void kernel_launch(void* const* d_in, const int* in_sizes, int n_in,
                              void* d_out, int out_size) {
    const float* x = (const float*)d_in[0];
    const float2* expkM = (const float2*)d_in[1];
    const float2* expkN = (const float2*)d_in[2];
    float* out = (float*)d_out;

    __half *bh0, *bh1;
    cudaGetSymbolAddress((void**)&bh0, g_bufh0);
    cudaGetSymbolAddress((void**)&bh1, g_bufh1);

    const size_t smem = (size_t)PADSZ * sizeof(float2);  // 17408 B
    dim3 tg(64, 64);

    fft_row_kernel<0, false><<<LROW, FFT_T, smem>>>(x, expkN, bh0);   // t (fp16)
    transpose_h_kernel<false><<<tg, 128>>>(bh0, bh1);                 // t^T (fp16)
    fft_row_kernel<1, true><<<LROW, FFT_T, smem>>>(bh1, expkM, bh0);  // y^T (fp16)
    transpose_h_kernel<true><<<tg, 128>>>(bh0, out);                  // y (fp32)
}